// round 1
// baseline (speedup 1.0000x reference)
#include <cuda_runtime.h>

// TransducerJoint: h[b,t,u,:] = f[b,t,:] + g[b,u,:] if t < f_len[b] && u < g_len[b] else 0
// B=16, T=256, U=96, H=512 (fp32). Output 805 MB -> pure HBM-write-bound.

#define B_ 16
#define T_ 256
#define U_ 96
#define H_ 512
#define H4_ (H_ / 4)      // 128 float4 per H-row
#define U_PER_BLK 4

__global__ __launch_bounds__(H4_) void transducer_joint_kernel(
    const float4* __restrict__ f,      // (B, T, H/4)
    const float4* __restrict__ g,      // (B, U, H/4)
    const int*    __restrict__ f_len,  // (B,)
    const int*    __restrict__ g_len,  // (B,)
    float4*       __restrict__ out)    // (B, T, U, H/4)
{
    const int h4 = threadIdx.x;        // 0..127
    const int u0 = blockIdx.x * U_PER_BLK;
    const int t  = blockIdx.y;
    const int b  = blockIdx.z;

    const bool t_ok = t < f_len[b];
    const int  gl   = g_len[b];

    // f row chunk: loaded once, reused for all 4 u's
    float4 f4 = f[((size_t)b * T_ + t) * H4_ + h4];

    const float4 zero = make_float4(0.f, 0.f, 0.f, 0.f);
    size_t base = (((size_t)b * T_ + t) * U_ + u0) * H4_ + h4;

#pragma unroll
    for (int du = 0; du < U_PER_BLK; ++du) {
        const int u = u0 + du;
        float4 r = zero;
        if (t_ok && u < gl) {
            float4 g4 = g[((size_t)b * U_ + u) * H4_ + h4];
            r.x = f4.x + g4.x;
            r.y = f4.y + g4.y;
            r.z = f4.z + g4.z;
            r.w = f4.w + g4.w;
        }
        out[base + (size_t)du * H4_] = r;
    }
}

extern "C" void kernel_launch(void* const* d_in, const int* in_sizes, int n_in,
                              void* d_out, int out_size)
{
    const float4* f     = (const float4*)d_in[0];
    const float4* g     = (const float4*)d_in[1];
    const int*    f_len = (const int*)d_in[2];
    const int*    g_len = (const int*)d_in[3];
    float4*       out   = (float4*)d_out;

    dim3 grid(U_ / U_PER_BLK, T_, B_);   // (24, 256, 16)
    dim3 block(H4_);                      // 128 threads
    transducer_joint_kernel<<<grid, block>>>(f, g, f_len, g_len, out);
}

// round 2
// speedup vs baseline: 1.1095x; 1.1095x over previous
#include <cuda_runtime.h>

// TransducerJoint: h[b,t,u,:] = f[b,t,:] + g[b,u,:] if t < f_len[b] && u < g_len[b] else 0
// B=16, T=256, U=96, H=512 (fp32). Output 805 MB -> pure HBM-write-bound.
// R2: streaming stores (__stcs) + 8 u-rows per block (16KB contiguous per block).

#define B_ 16
#define T_ 256
#define U_ 96
#define H_ 512
#define H4_ (H_ / 4)      // 128 float4 per H-row
#define U_PER_BLK 8

__global__ __launch_bounds__(H4_) void transducer_joint_kernel(
    const float4* __restrict__ f,      // (B, T, H/4)
    const float4* __restrict__ g,      // (B, U, H/4)
    const int*    __restrict__ f_len,  // (B,)
    const int*    __restrict__ g_len,  // (B,)
    float4*       __restrict__ out)    // (B, T, U, H/4)
{
    const int h4 = threadIdx.x;        // 0..127
    const int u0 = blockIdx.x * U_PER_BLK;
    const int t  = blockIdx.y;
    const int b  = blockIdx.z;

    const bool t_ok = t < f_len[b];
    const int  gl   = g_len[b];

    // f row chunk: loaded once, reused for all 8 u's
    const float4 f4 = f[((size_t)b * T_ + t) * H4_ + h4];

    const float4 zero = make_float4(0.f, 0.f, 0.f, 0.f);
    float4* obase = out + (((size_t)b * T_ + t) * U_ + u0) * H4_ + h4;
    const float4* gbase = g + ((size_t)b * U_ + u0) * H4_ + h4;

#pragma unroll
    for (int du = 0; du < U_PER_BLK; ++du) {
        const int u = u0 + du;
        float4 r = zero;
        if (t_ok && u < gl) {
            float4 g4 = __ldg(gbase + (size_t)du * H4_);
            r.x = f4.x + g4.x;
            r.y = f4.y + g4.y;
            r.z = f4.z + g4.z;
            r.w = f4.w + g4.w;
        }
        // streaming store: output is never re-read; evict-first in L2
        __stcs(obase + (size_t)du * H4_, r);
    }
}

extern "C" void kernel_launch(void* const* d_in, const int* in_sizes, int n_in,
                              void* d_out, int out_size)
{
    const float4* f     = (const float4*)d_in[0];
    const float4* g     = (const float4*)d_in[1];
    const int*    f_len = (const int*)d_in[2];
    const int*    g_len = (const int*)d_in[3];
    float4*       out   = (float4*)d_out;

    dim3 grid(U_ / U_PER_BLK, T_, B_);   // (12, 256, 16)
    dim3 block(H4_);                      // 128 threads
    transducer_joint_kernel<<<grid, block>>>(f, g, f_len, g_len, out);
}